// round 2
// baseline (speedup 1.0000x reference)
#include <cuda_runtime.h>

#define BB 4
#define SS 2048
#define DD 2048          // D_IN = D_STATE = D_OUT
#define NH 16
#define HH 128

// Scratch (device globals: allocation-free rule)
static __device__ float g_xp[(size_t)BB * SS * DD];
static __device__ float g_hs[(size_t)BB * SS * DD];

typedef unsigned long long ull;

__device__ __forceinline__ ull pack2(float x, float y) {
    ull r; asm("mov.b64 %0, {%1,%2};" : "=l"(r) : "f"(x), "f"(y)); return r;
}
__device__ __forceinline__ float2 unpack2(ull v) {
    float lo, hi; asm("mov.b64 {%0,%1}, %2;" : "=f"(lo), "=f"(hi) : "l"(v));
    return make_float2(lo, hi);
}
// packed fp32x2 FMA (Blackwell): c = a*b + c elementwise on pairs
__device__ __forceinline__ void fma2(ull& c, ull a, ull b) {
    asm("fma.rn.f32x2 %0, %1, %2, %3;" : "=l"(c) : "l"(a), "l"(b), "l"(c));
}

// ---------------------------------------------------------------------------
// fp32 SIMT GEMM: C[M,N] = A[M,K] @ B[K,N] (+ bias). 128x128x16 tile,
// 256 threads, 8x8 microtile held as 8x4 f32x2 accumulators.
// M,N,K multiples of 128/128/16 (true for all calls here).
// ---------------------------------------------------------------------------
template <bool BIAS>
__global__ void __launch_bounds__(256, 2)
gemm128(const float* __restrict__ A, const float* __restrict__ Bg,
        const float* __restrict__ bias, float* __restrict__ C,
        int K, int N) {
    __shared__ __align__(16) float As[2][16][128];   // As[k][m]
    __shared__ __align__(16) float Bs[2][16][128];   // Bs[k][n]

    const int tid = threadIdx.x;
    const int bm = blockIdx.y * 128;
    const int bn = blockIdx.x * 128;
    const int tx = tid & 15;          // 16 cols of microtiles
    const int ty = tid >> 4;          // 16 rows of microtiles

    // global->smem load mapping (each thread: 2 float4 from A, 2 from B)
    const int aRow0 = tid >> 2;                // 0..63
    const int aRow1 = aRow0 + 64;              // 64..127
    const int aCol0 = (tid & 3) << 2;          // 0,4,8,12
    const int bRow0 = tid >> 5;                // 0..7
    const int bRow1 = bRow0 + 8;               // 8..15
    const int bCol0 = (tid & 31) << 2;         // 0..124

    const float* Ap0 = A + (size_t)(bm + aRow0) * K + aCol0;
    const float* Ap1 = A + (size_t)(bm + aRow1) * K + aCol0;
    const float* Bp0 = Bg + (size_t)bRow0 * N + bn + bCol0;
    const float* Bp1 = Bg + (size_t)bRow1 * N + bn + bCol0;

    float4 ra0 = *(const float4*)Ap0;
    float4 ra1 = *(const float4*)Ap1;
    float4 rb0 = *(const float4*)Bp0;
    float4 rb1 = *(const float4*)Bp1;

    ull acc[8][4];
#pragma unroll
    for (int i = 0; i < 8; i++) {
        acc[i][0] = 0ull; acc[i][1] = 0ull; acc[i][2] = 0ull; acc[i][3] = 0ull;
    }

    // stage 0
    As[0][aCol0 + 0][aRow0] = ra0.x; As[0][aCol0 + 1][aRow0] = ra0.y;
    As[0][aCol0 + 2][aRow0] = ra0.z; As[0][aCol0 + 3][aRow0] = ra0.w;
    As[0][aCol0 + 0][aRow1] = ra1.x; As[0][aCol0 + 1][aRow1] = ra1.y;
    As[0][aCol0 + 2][aRow1] = ra1.z; As[0][aCol0 + 3][aRow1] = ra1.w;
    *(float4*)&Bs[0][bRow0][bCol0] = rb0;
    *(float4*)&Bs[0][bRow1][bCol0] = rb1;
    __syncthreads();

    const int ntiles = K >> 4;
    int s = 0;
    for (int t = 0; t < ntiles; t++) {
        if (t + 1 < ntiles) {
            ra0 = *(const float4*)(Ap0 + (t + 1) * 16);
            ra1 = *(const float4*)(Ap1 + (t + 1) * 16);
            rb0 = *(const float4*)(Bp0 + (size_t)(t + 1) * 16 * N);
            rb1 = *(const float4*)(Bp1 + (size_t)(t + 1) * 16 * N);
        }
#pragma unroll
        for (int kk = 0; kk < 16; kk++) {
            float4 av0 = *(const float4*)&As[s][kk][ty * 8];
            float4 av1 = *(const float4*)&As[s][kk][ty * 8 + 4];
            ulonglong2 bq0 = *(const ulonglong2*)&Bs[s][kk][tx * 8];
            ulonglong2 bq1 = *(const ulonglong2*)&Bs[s][kk][tx * 8 + 4];
            float a[8] = {av0.x, av0.y, av0.z, av0.w, av1.x, av1.y, av1.z, av1.w};
#pragma unroll
            for (int i = 0; i < 8; i++) {
                ull ad = pack2(a[i], a[i]);
                fma2(acc[i][0], ad, bq0.x);
                fma2(acc[i][1], ad, bq0.y);
                fma2(acc[i][2], ad, bq1.x);
                fma2(acc[i][3], ad, bq1.y);
            }
        }
        if (t + 1 < ntiles) {
            const int sn = s ^ 1;
            As[sn][aCol0 + 0][aRow0] = ra0.x; As[sn][aCol0 + 1][aRow0] = ra0.y;
            As[sn][aCol0 + 2][aRow0] = ra0.z; As[sn][aCol0 + 3][aRow0] = ra0.w;
            As[sn][aCol0 + 0][aRow1] = ra1.x; As[sn][aCol0 + 1][aRow1] = ra1.y;
            As[sn][aCol0 + 2][aRow1] = ra1.z; As[sn][aCol0 + 3][aRow1] = ra1.w;
            *(float4*)&Bs[sn][bRow0][bCol0] = rb0;
            *(float4*)&Bs[sn][bRow1][bCol0] = rb1;
        }
        __syncthreads();
        s ^= 1;
    }

    float bv[8];
    if (BIAS) {
        float4 t0 = *(const float4*)&bias[bn + tx * 8];
        float4 t1 = *(const float4*)&bias[bn + tx * 8 + 4];
        bv[0] = t0.x; bv[1] = t0.y; bv[2] = t0.z; bv[3] = t0.w;
        bv[4] = t1.x; bv[5] = t1.y; bv[6] = t1.z; bv[7] = t1.w;
    }
#pragma unroll
    for (int i = 0; i < 8; i++) {
        float2 c0 = unpack2(acc[i][0]);
        float2 c1 = unpack2(acc[i][1]);
        float2 c2 = unpack2(acc[i][2]);
        float2 c3 = unpack2(acc[i][3]);
        if (BIAS) {
            c0.x += bv[0]; c0.y += bv[1]; c1.x += bv[2]; c1.y += bv[3];
            c2.x += bv[4]; c2.y += bv[5]; c3.x += bv[6]; c3.y += bv[7];
        }
        float* crow = C + (size_t)(bm + ty * 8 + i) * N + bn + tx * 8;
        *(float4*)crow = make_float4(c0.x, c0.y, c1.x, c1.y);
        *(float4*)(crow + 4) = make_float4(c2.x, c2.y, c3.x, c3.y);
    }
}

// ---------------------------------------------------------------------------
// Recurrence: 64 CTAs = one per (batch, head) chain. 128 threads: thread j
// owns output element j, with W[:,j] resident in 64 f32x2 registers.
// h double-buffered in SMEM; xp prefetched depth-8 via register ring.
// ---------------------------------------------------------------------------
__global__ void __launch_bounds__(128, 1)
rnn_kernel(const float* __restrict__ xp, const float* __restrict__ init_state,
           const float* __restrict__ state_w, float* __restrict__ hs,
           float* __restrict__ out_state) {
    const int b = blockIdx.x >> 4;
    const int n = blockIdx.x & 15;
    const int j = threadIdx.x;

    __shared__ __align__(16) float h_sh[2][HH];

    // load column j of W[n]: w2[m] = {W[2m][j], W[2m+1][j]}
    ull w2[64];
    const float* W = state_w + (size_t)n * HH * HH + j;
#pragma unroll
    for (int m = 0; m < 64; m++)
        w2[m] = pack2(W[(2 * m) * HH], W[(2 * m + 1) * HH]);

    h_sh[0][j] = init_state[b * DD + n * HH + j];

    const float* xb = xp + ((size_t)b * SS * NH + n) * HH + j;  // stride per t: DD
    float* hb = hs + ((size_t)b * SS * NH + n) * HH + j;

    float xq[8];
#pragma unroll
    for (int p = 0; p < 8; p++) xq[p] = xb[(size_t)p * DD];

    __syncthreads();

    int cur = 0;
    for (int t = 0; t < SS; t++) {
        const ulonglong2* hv = (const ulonglong2*)h_sh[cur];
        ull a0 = 0ull, a1 = 0ull, a2 = 0ull, a3 = 0ull;
#pragma unroll
        for (int m = 0; m < 32; m += 2) {
            ulonglong2 ha = hv[m];
            ulonglong2 hc = hv[m + 1];
            fma2(a0, ha.x, w2[2 * m]);
            fma2(a1, ha.y, w2[2 * m + 1]);
            fma2(a2, hc.x, w2[2 * m + 2]);
            fma2(a3, hc.y, w2[2 * m + 3]);
        }
        float2 f0 = unpack2(a0), f1 = unpack2(a1);
        float2 f2 = unpack2(a2), f3 = unpack2(a3);
        float sum = ((f0.x + f0.y) + (f1.x + f1.y)) +
                    ((f2.x + f2.y) + (f3.x + f3.y));

        float xv = xq[t & 7];
        if (t + 8 < SS) xq[t & 7] = xb[(size_t)(t + 8) * DD];

        float hn = tanhf(sum + xv);
        hb[(size_t)t * DD] = hn;

        const int nxt = cur ^ 1;
        h_sh[nxt][j] = hn;
        __syncthreads();
        cur = nxt;
    }

    if (out_state) out_state[b * DD + n * HH + j] = h_sh[cur][j];
}

// ---------------------------------------------------------------------------
extern "C" void kernel_launch(void* const* d_in, const int* in_sizes, int n_in,
                              void* d_out, int out_size) {
    const float* x = (const float*)d_in[0];
    const float* input_state = (const float*)d_in[1];
    const float* Wi = (const float*)d_in[2];
    const float* bias = (const float*)d_in[3];
    const float* state_w = (const float*)d_in[4];
    const float* Wo = (const float*)d_in[5];
    float* out = (float*)d_out;

    float *xp = nullptr, *hs = nullptr;
    cudaGetSymbolAddress((void**)&xp, g_xp);
    cudaGetSymbolAddress((void**)&hs, g_hs);

    const size_t out_elems = (size_t)BB * SS * DD;
    float* state_out = nullptr;
    if ((size_t)out_size >= out_elems + (size_t)BB * DD)
        state_out = out + out_elems;

    dim3 grid(DD / 128, (BB * SS) / 128);  // (16, 64)

    // 1) xp = x @ Wi + b
    gemm128<true><<<grid, 256>>>(x, Wi, bias, xp, DD, DD);
    // 2) sequential recurrence -> hs (+ final state)
    rnn_kernel<<<64, 128>>>(xp, input_state, state_w, hs, state_out);
    // 3) out = hs @ Wo
    gemm128<false><<<grid, 256>>>(hs, Wo, nullptr, out, DD, DD);
}

// round 5
// speedup vs baseline: 1.7083x; 1.7083x over previous
#include <cuda_runtime.h>
#include <cuda_bf16.h>
#include <cstdint>

#define BB 4
#define SS 2048
#define DD 2048          // D_IN = D_STATE = D_OUT
#define NH 16
#define HH 128

// ------------------------- global scratch (no allocs) -----------------------
static __device__ float g_xp[(size_t)BB * SS * DD];                  // 64MB
static __device__ __nv_bfloat16 g_xh[(size_t)BB * SS * DD];          // 32MB
static __device__ __nv_bfloat16 g_xl[(size_t)BB * SS * DD];
static __device__ __nv_bfloat16 g_hsh[(size_t)BB * SS * DD];
static __device__ __nv_bfloat16 g_hsl[(size_t)BB * SS * DD];
static __device__ __nv_bfloat16 g_WiTh[(size_t)DD * DD];             // 8MB
static __device__ __nv_bfloat16 g_WiTl[(size_t)DD * DD];
static __device__ __nv_bfloat16 g_WoTh[(size_t)DD * DD];
static __device__ __nv_bfloat16 g_WoTl[(size_t)DD * DD];

typedef unsigned long long ull;

__device__ __forceinline__ ull pack2(float x, float y) {
    ull r; asm("mov.b64 %0, {%1,%2};" : "=l"(r) : "f"(x), "f"(y)); return r;
}
__device__ __forceinline__ float2 unpack2(ull v) {
    float lo, hi; asm("mov.b64 {%0,%1}, %2;" : "=f"(lo), "=f"(hi) : "l"(v));
    return make_float2(lo, hi);
}
__device__ __forceinline__ void fma2(ull& c, ull a, ull b) {
    asm("fma.rn.f32x2 %0, %1, %2, %3;" : "=l"(c) : "l"(a), "l"(b), "l"(c));
}

__device__ __forceinline__ uint32_t smem_u32(const void* p) {
    uint32_t a;
    asm("{ .reg .u64 t; cvta.to.shared.u64 t, %1; cvt.u32.u64 %0, t; }"
        : "=r"(a) : "l"(p));
    return a;
}
__device__ __forceinline__ void cp16(uint32_t s, const void* g) {
    asm volatile("cp.async.cg.shared.global [%0], [%1], 16;"
                 :: "r"(s), "l"(g) : "memory");
}
__device__ __forceinline__ void ldmx4(uint32_t* r, uint32_t addr) {
    asm volatile("ldmatrix.sync.aligned.m8n8.x4.shared.b16 {%0,%1,%2,%3}, [%4];"
                 : "=r"(r[0]), "=r"(r[1]), "=r"(r[2]), "=r"(r[3]) : "r"(addr));
}
__device__ __forceinline__ void mma_bf(float* c, const uint32_t* a,
                                       const uint32_t* b) {
    asm volatile(
        "mma.sync.aligned.m16n8k16.row.col.f32.bf16.bf16.f32 "
        "{%0,%1,%2,%3}, {%4,%5,%6,%7}, {%8,%9}, {%0,%1,%2,%3};"
        : "+f"(c[0]), "+f"(c[1]), "+f"(c[2]), "+f"(c[3])
        : "r"(a[0]), "r"(a[1]), "r"(a[2]), "r"(a[3]), "r"(b[0]), "r"(b[1]));
}

// ---------------------------------------------------------------------------
// elementwise split fp32 -> bf16 (hi, lo). n must be multiple of 4.
// ---------------------------------------------------------------------------
__global__ void __launch_bounds__(256)
split_f32(const float4* __restrict__ in, __nv_bfloat162* __restrict__ hi,
          __nv_bfloat162* __restrict__ lo) {
    int i = blockIdx.x * 256 + threadIdx.x;
    float4 v = in[i];
    __nv_bfloat16 h0 = __float2bfloat16(v.x), h1 = __float2bfloat16(v.y);
    __nv_bfloat16 h2 = __float2bfloat16(v.z), h3 = __float2bfloat16(v.w);
    hi[2 * i + 0] = __halves2bfloat162(h0, h1);
    hi[2 * i + 1] = __halves2bfloat162(h2, h3);
    lo[2 * i + 0] = __halves2bfloat162(
        __float2bfloat16(v.x - __bfloat162float(h0)),
        __float2bfloat16(v.y - __bfloat162float(h1)));
    lo[2 * i + 1] = __halves2bfloat162(
        __float2bfloat16(v.z - __bfloat162float(h2)),
        __float2bfloat16(v.w - __bfloat162float(h3)));
}

// ---------------------------------------------------------------------------
// transpose 2048x2048 fp32 + split -> bf16 hi/lo (out[n][k] = in[k][n])
// ---------------------------------------------------------------------------
__global__ void __launch_bounds__(256)
transpose_split(const float* __restrict__ in, __nv_bfloat16* __restrict__ oh,
                __nv_bfloat16* __restrict__ ol) {
    __shared__ float tile[32][33];
    int x = blockIdx.x * 32 + threadIdx.x;
    int y = blockIdx.y * 32 + threadIdx.y;
#pragma unroll
    for (int i = 0; i < 32; i += 8)
        tile[threadIdx.y + i][threadIdx.x] = in[(size_t)(y + i) * DD + x];
    __syncthreads();
    x = blockIdx.y * 32 + threadIdx.x;
    y = blockIdx.x * 32 + threadIdx.y;
#pragma unroll
    for (int i = 0; i < 32; i += 8) {
        float v = tile[threadIdx.x][threadIdx.y + i];
        __nv_bfloat16 h = __float2bfloat16(v);
        oh[(size_t)(y + i) * DD + x] = h;
        ol[(size_t)(y + i) * DD + x] =
            __float2bfloat16(v - __bfloat162float(h));
    }
}

// ---------------------------------------------------------------------------
// 3x bf16-split GEMM via mma.sync: C[M,2048] = A @ BT^T (+bias)
//   A given as (Ah, Al) bf16 [M,K] row-major; BT as (Bh, Bl) bf16 [N,K].
//   128x128 CTA tile, K_tile=32, 8 warps (4m x 2n), 2-stage cp.async.
// ---------------------------------------------------------------------------
#define KT 32
#define PADK 40                         // smem row stride in bf16 elems (80B)
#define OPB (128 * PADK * 2)            // 10240 B per operand tile
#define STAGEB (4 * OPB)                // 40960 B
#define SMEMB (2 * STAGEB)              // 81920 B

template <bool BIAS>
__global__ void __launch_bounds__(256, 2)
gemm_bf3(const __nv_bfloat16* __restrict__ Ah,
         const __nv_bfloat16* __restrict__ Al,
         const __nv_bfloat16* __restrict__ Bh,
         const __nv_bfloat16* __restrict__ Bl,
         const float* __restrict__ bias, float* __restrict__ C) {
    extern __shared__ __align__(128) char smem[];
    const uint32_t sb = smem_u32(smem);
    const int tid = threadIdx.x;
    const int lane = tid & 31;
    const int wid = tid >> 5;
    const int wm = wid & 3;             // 4 m-blocks of 32 rows
    const int wn = wid >> 2;            // 2 n-blocks of 64 cols
    const size_t bm = (size_t)blockIdx.y * 128;
    const size_t bn = (size_t)blockIdx.x * 128;

    // per-thread cp.async mapping: 2 16B chunks per operand
    const __nv_bfloat16* gsrc[4][2];
    uint32_t sdst[4][2];
    {
        const __nv_bfloat16* bases[4] = {Ah, Al, Bh, Bl};
#pragma unroll
        for (int op = 0; op < 4; op++)
#pragma unroll
            for (int i = 0; i < 2; i++) {
                int idx = tid * 2 + i;
                int r = idx >> 2, c = idx & 3;
                size_t grow = (op < 2 ? bm : bn) + r;
                gsrc[op][i] = bases[op] + grow * DD + c * 8;
                sdst[op][i] = sb + op * OPB + r * (PADK * 2) + c * 16;
            }
    }

    // fragment smem addresses
    const uint32_t aAddr = sb + (wm * 32 + (lane & 15)) * (PADK * 2) +
                           (lane >> 4) * 16;
    const int n_off = (lane & 7) + ((lane >> 4) & 1) * 8;
    const int k_off = ((lane >> 3) & 1) * 16;
    const uint32_t bAddr = sb + 2 * OPB + (wn * 64 + n_off) * (PADK * 2) + k_off;

    float acc[64];
#pragma unroll
    for (int i = 0; i < 64; i++) acc[i] = 0.0f;

    // prologue: stage 0 <- k-tile 0
#pragma unroll
    for (int op = 0; op < 4; op++)
#pragma unroll
        for (int i = 0; i < 2; i++)
            cp16(sdst[op][i], gsrc[op][i]);
    asm volatile("cp.async.commit_group;" ::: "memory");

    const int ntiles = DD / KT;  // 64
    for (int t = 0; t < ntiles; t++) {
        asm volatile("cp.async.wait_group 0;" ::: "memory");
        __syncthreads();

        if (t + 1 < ntiles) {
            const uint32_t so = ((t + 1) & 1) * STAGEB;
            const int ko = (t + 1) * KT;
#pragma unroll
            for (int op = 0; op < 4; op++)
#pragma unroll
                for (int i = 0; i < 2; i++)
                    cp16(sdst[op][i] + so, gsrc[op][i] + ko);
            asm volatile("cp.async.commit_group;" ::: "memory");
        }

        const uint32_t so = (t & 1) * STAGEB;
#pragma unroll
        for (int kk = 0; kk < 2; kk++) {
            uint32_t ah[2][4], al[2][4];
            ldmx4(ah[0], aAddr + so + kk * 32);
            ldmx4(ah[1], aAddr + so + 16 * (PADK * 2) + kk * 32);
            ldmx4(al[0], aAddr + so + OPB + kk * 32);
            ldmx4(al[1], aAddr + so + OPB + 16 * (PADK * 2) + kk * 32);
#pragma unroll
            for (int p = 0; p < 4; p++) {
                uint32_t bh[4], bl[4];
                ldmx4(bh, bAddr + so + p * 16 * (PADK * 2) + kk * 32);
                ldmx4(bl, bAddr + so + OPB + p * 16 * (PADK * 2) + kk * 32);
#pragma unroll
                for (int mt = 0; mt < 2; mt++) {
                    float* c0 = &acc[(mt * 8 + 2 * p) * 4];
                    float* c1 = &acc[(mt * 8 + 2 * p + 1) * 4];
                    mma_bf(c0, ah[mt], bh + 0);
                    mma_bf(c1, ah[mt], bh + 2);
                    mma_bf(c0, al[mt], bh + 0);
                    mma_bf(c1, al[mt], bh + 2);
                    mma_bf(c0, ah[mt], bl + 0);
                    mma_bf(c1, ah[mt], bl + 2);
                }
            }
        }
        __syncthreads();
    }

    // epilogue
#pragma unroll
    for (int mt = 0; mt < 2; mt++) {
        const size_t r0 = bm + wm * 32 + mt * 16 + (lane >> 2);
#pragma unroll
        for (int nt = 0; nt < 8; nt++) {
            const size_t col = bn + wn * 64 + nt * 8 + (lane & 3) * 2;
            const float* a = &acc[(mt * 8 + nt) * 4];
            float2 v0 = make_float2(a[0], a[1]);
            float2 v1 = make_float2(a[2], a[3]);
            if (BIAS) {
                float2 bv = *(const float2*)&bias[col];
                v0.x += bv.x; v0.y += bv.y;
                v1.x += bv.x; v1.y += bv.y;
            }
            *(float2*)&C[r0 * DD + col] = v0;
            *(float2*)&C[(r0 + 8) * DD + col] = v1;
        }
    }
}

// ---------------------------------------------------------------------------
// Recurrence: 64 chains, W columns in regs; emits hs as bf16 hi/lo split.
// ---------------------------------------------------------------------------
__global__ void __launch_bounds__(128, 1)
rnn_kernel(const float* __restrict__ xp, const float* __restrict__ init_state,
           const float* __restrict__ state_w,
           __nv_bfloat16* __restrict__ hs_h, __nv_bfloat16* __restrict__ hs_l,
           float* __restrict__ out_state) {
    const int b = blockIdx.x >> 4;
    const int n = blockIdx.x & 15;
    const int j = threadIdx.x;

    __shared__ __align__(16) float h_sh[2][HH];

    ull w2[64];
    const float* W = state_w + (size_t)n * HH * HH + j;
#pragma unroll
    for (int m = 0; m < 64; m++)
        w2[m] = pack2(W[(2 * m) * HH], W[(2 * m + 1) * HH]);

    h_sh[0][j] = init_state[b * DD + n * HH + j];

    const float* xb = xp + ((size_t)b * SS * NH + n) * HH + j;
    __nv_bfloat16* hbh = hs_h + ((size_t)b * SS * NH + n) * HH + j;
    __nv_bfloat16* hbl = hs_l + ((size_t)b * SS * NH + n) * HH + j;

    float xq[8];
#pragma unroll
    for (int p = 0; p < 8; p++) xq[p] = xb[(size_t)p * DD];

    __syncthreads();

    int cur = 0;
    for (int t = 0; t < SS; t++) {
        const ulonglong2* hv = (const ulonglong2*)h_sh[cur];
        ull a0 = 0ull, a1 = 0ull, a2 = 0ull, a3 = 0ull;
#pragma unroll
        for (int m = 0; m < 32; m += 2) {
            ulonglong2 ha = hv[m];
            ulonglong2 hc = hv[m + 1];
            fma2(a0, ha.x, w2[2 * m]);
            fma2(a1, ha.y, w2[2 * m + 1]);
            fma2(a2, hc.x, w2[2 * m + 2]);
            fma2(a3, hc.y, w2[2 * m + 3]);
        }
        float2 f0 = unpack2(a0), f1 = unpack2(a1);
        float2 f2 = unpack2(a2), f3 = unpack2(a3);
        float sum = ((f0.x + f0.y) + (f1.x + f1.y)) +
                    ((f2.x + f2.y) + (f3.x + f3.y));

        float xv = xq[t & 7];
        if (t + 8 < SS) xq[t & 7] = xb[(size_t)(t + 8) * DD];

        float hn = tanhf(sum + xv);
        __nv_bfloat16 hh = __float2bfloat16(hn);
        hbh[(size_t)t * DD] = hh;
        hbl[(size_t)t * DD] = __float2bfloat16(hn - __bfloat162float(hh));

        const int nxt = cur ^ 1;
        h_sh[nxt][j] = hn;
        __syncthreads();
        cur = nxt;
    }

    if (out_state) out_state[b * DD + n * HH + j] = h_sh[cur][j];
}

// ---------------------------------------------------------------------------
extern "C" void kernel_launch(void* const* d_in, const int* in_sizes, int n_in,
                              void* d_out, int out_size) {
    const float* x = (const float*)d_in[0];
    const float* input_state = (const float*)d_in[1];
    const float* Wi = (const float*)d_in[2];
    const float* bias = (const float*)d_in[3];
    const float* state_w = (const float*)d_in[4];
    const float* Wo = (const float*)d_in[5];
    float* out = (float*)d_out;

    float* xp = nullptr;
    __nv_bfloat16 *xh, *xl, *hsh, *hsl, *WiTh, *WiTl, *WoTh, *WoTl;
    cudaGetSymbolAddress((void**)&xp, g_xp);
    cudaGetSymbolAddress((void**)&xh, g_xh);
    cudaGetSymbolAddress((void**)&xl, g_xl);
    cudaGetSymbolAddress((void**)&hsh, g_hsh);
    cudaGetSymbolAddress((void**)&hsl, g_hsl);
    cudaGetSymbolAddress((void**)&WiTh, g_WiTh);
    cudaGetSymbolAddress((void**)&WiTl, g_WiTl);
    cudaGetSymbolAddress((void**)&WoTh, g_WoTh);
    cudaGetSymbolAddress((void**)&WoTl, g_WoTl);

    cudaFuncSetAttribute(gemm_bf3<true>,
                         cudaFuncAttributeMaxDynamicSharedMemorySize, SMEMB);
    cudaFuncSetAttribute(gemm_bf3<false>,
                         cudaFuncAttributeMaxDynamicSharedMemorySize, SMEMB);

    const size_t out_elems = (size_t)BB * SS * DD;
    float* state_out = nullptr;
    if ((size_t)out_size >= out_elems + (size_t)BB * DD)
        state_out = out + out_elems;

    // 0) operand preparation
    split_f32<<<(BB * SS * DD) / 4 / 256, 256>>>(
        (const float4*)x, (__nv_bfloat162*)xh, (__nv_bfloat162*)xl);
    dim3 tgrid(DD / 32, DD / 32), tblk(32, 8);
    transpose_split<<<tgrid, tblk>>>(Wi, WiTh, WiTl);
    transpose_split<<<tgrid, tblk>>>(Wo, WoTh, WoTl);

    dim3 ggrid(DD / 128, (BB * SS) / 128);  // (16, 64)
    // 1) xp = x @ Wi + b
    gemm_bf3<true><<<ggrid, 256, SMEMB>>>(xh, xl, WiTh, WiTl, bias, xp);
    // 2) recurrence -> hs (bf16 hi/lo) + final state
    rnn_kernel<<<64, 128>>>(xp, input_state, state_w, hsh, hsl, state_out);
    // 3) out = hs @ Wo
    gemm_bf3<false><<<ggrid, 256, SMEMB>>>(hsh, hsl, WoTh, WoTl, nullptr, out);
}